// round 14
// baseline (speedup 1.0000x reference)
#include <cuda_runtime.h>
#include <cuda_bf16.h>
#include <cstdint>

#define N_NODES 100000
#define N_EDGES 1600000
#define N_LAB   200000
#define D       128
#define D4      32    // D/4 floats
#define DW      64    // D/2 = 32-bit words per row of bf16
#define NB      391   // ceil(N_NODES / 256)
#define GEMM_CTAS 782
#define NHALF   50048 // 391 * 128 (CTA-aligned node split)

// ---------------- static device scratch (no allocations allowed) ----------
__device__ float    g_h[(size_t)N_NODES * D];  // GEMM output (pre-aggregation)
__device__ float    g_z[(size_t)N_NODES * D];  // final aggregated features
__device__ float    g_dinv[N_NODES];
__device__ int      g_cnt[N_NODES];
__device__ int      g_rowptr[N_NODES + 1];
__device__ int      g_cursor[N_NODES];
__device__ int      g_bsum[NB];
__device__ int      g_boff[NB];
__device__ int2     g_csr[N_EDGES];            // {src, bitcast(norm weight)}
__device__ int      g_is64;
// split-bf16 A tables for layer 2 (written by agg1; padding rows stay 0)
__device__ uint32_t g_ahi[(size_t)GEMM_CTAS * 128 * DW];
__device__ uint32_t g_alo[(size_t)GEMM_CTAS * 128 * DW];
__device__ uint32_t g_w1hi[D * DW], g_w1lo[D * DW];  // (n, kword)
__device__ uint32_t g_w2hi[D * DW], g_w2lo[D * DW];

// ---------------- helpers --------------------------------------------------
__device__ __forceinline__ void split_pack(float v0, float v1,
                                           uint32_t& hi, uint32_t& lo) {
    __nv_bfloat16 h0 = __float2bfloat16(v0);
    __nv_bfloat16 h1 = __float2bfloat16(v1);
    __nv_bfloat16 l0 = __float2bfloat16(v0 - __bfloat162float(h0));
    __nv_bfloat16 l1 = __float2bfloat16(v1 - __bfloat162float(h1));
    hi = (uint32_t)__bfloat16_as_ushort(h0) |
         ((uint32_t)__bfloat16_as_ushort(h1) << 16);
    lo = (uint32_t)__bfloat16_as_ushort(l0) |
         ((uint32_t)__bfloat16_as_ushort(l1) << 16);
}

// ---------------- dtype autodetect + counter init (fused) ------------------
__global__ void k_detect_init(const int* __restrict__ ei_raw) {
    int i = blockIdx.x * blockDim.x + threadIdx.x;
    if (i < N_NODES) g_cnt[i] = 0;
    if (i == 0) {
        int all_zero = 1;
        for (int j = 0; j < 32; j++)
            if (ei_raw[2 * j + 1] != 0) { all_zero = 0; break; }
        g_is64 = all_zero;
    }
}

__device__ __forceinline__ int load_idx(const void* p, size_t i) {
    return g_is64 ? (int)((const long long*)p)[i] : ((const int*)p)[i];
}

// ---------------- degree / norm prep --------------------------------------
__global__ void k_cnt_acc(const void* __restrict__ ei) {
    int e = blockIdx.x * blockDim.x + threadIdx.x;
    if (e < N_EDGES) atomicAdd(&g_cnt[load_idx(ei, (size_t)N_EDGES + e)], 1);
}

__global__ void k_dinv() {
    int i = blockIdx.x * blockDim.x + threadIdx.x;
    if (i < N_NODES) g_dinv[i] = rsqrtf((float)(g_cnt[i] + 1));  // +1 self loop
}

// ---------------- CSR build: 3-kernel prefix sum + binned fill -------------
__global__ void k_scan_block() {
    __shared__ int sm[256];
    int b = blockIdx.x, t = threadIdx.x;
    int i = b * 256 + t;
    int v = (i < N_NODES) ? g_cnt[i] : 0;
    sm[t] = v;
    __syncthreads();
    for (int off = 1; off < 256; off <<= 1) {
        int add = (t >= off) ? sm[t - off] : 0;
        __syncthreads();
        sm[t] += add;
        __syncthreads();
    }
    if (i < N_NODES) g_rowptr[i] = sm[t] - v;
    if (t == 255)    g_bsum[b] = sm[255];
}

__global__ void k_scan_top() {
    __shared__ int sm[512];
    int t = threadIdx.x;
    int v = (t < NB) ? g_bsum[t] : 0;
    sm[t] = v;
    __syncthreads();
    for (int off = 1; off < 512; off <<= 1) {
        int add = (t >= off) ? sm[t - off] : 0;
        __syncthreads();
        sm[t] += add;
        __syncthreads();
    }
    if (t < NB) g_boff[t] = sm[t] - v;
    if (t == 0) g_rowptr[N_NODES] = sm[511];
}

__global__ void k_scan_add() {
    int i = blockIdx.x * blockDim.x + threadIdx.x;
    if (i < N_NODES) {
        int r = g_rowptr[i] + g_boff[i >> 8];
        g_rowptr[i] = r;
        g_cursor[i] = r;
    }
}

__global__ void k_fill(const void* __restrict__ ei) {
    int e = blockIdx.x * blockDim.x + threadIdx.x;
    if (e < N_EDGES) {
        int s = load_idx(ei, e);
        int d = load_idx(ei, (size_t)N_EDGES + e);
        float w = g_dinv[s] * g_dinv[d];
        int pos = atomicAdd(&g_cursor[d], 1);
        g_csr[pos] = make_int2(s, __float_as_int(w));
    }
}

// ---------------- W conversion (once per call, tiny) -----------------------
__global__ void k_wconv(const float* __restrict__ W1,
                        const float* __restrict__ W2) {
    int idx = blockIdx.x * 256 + threadIdx.x;      // 0..16383
    int mat = idx >> 13;
    int j = idx & 8191;
    int n = j >> 6, kw = j & 63;
    const float* Wm = mat ? W2 : W1;
    float v0 = Wm[(size_t)(2 * kw) * D + n];
    float v1 = Wm[(size_t)(2 * kw + 1) * D + n];
    uint32_t hi, lo;
    split_pack(v0, v1, hi, lo);
    if (mat) { g_w2hi[j] = hi; g_w2lo[j] = lo; }
    else     { g_w1hi[j] = hi; g_w1lo[j] = lo; }
}

// ================= HMMA GEMM (mma.sync, split-bf16 x3) =====================
__device__ __forceinline__ void mma_bf16(float* d, const uint32_t* a,
                                         uint32_t b0, uint32_t b1) {
    asm volatile(
        "mma.sync.aligned.m16n8k16.row.col.f32.bf16.bf16.f32 "
        "{%0,%1,%2,%3}, {%4,%5,%6,%7}, {%8,%9}, {%0,%1,%2,%3};"
        : "+f"(d[0]), "+f"(d[1]), "+f"(d[2]), "+f"(d[3])
        : "r"(a[0]), "r"(a[1]), "r"(a[2]), "r"(a[3]), "r"(b0), "r"(b1));
}

// Layer-1 GEMM: A = fp32 x, converted to split-bf16 in-register.
__global__ void __launch_bounds__(256, 2)
k_gemm_x(const float* __restrict__ X,
         const uint32_t* __restrict__ Bhi, const uint32_t* __restrict__ Blo,
         float* __restrict__ C, int M) {
    int tid = threadIdx.x, wid = tid >> 5, lane = tid & 31;
    int g = lane >> 2, t4 = lane & 3;
    int m0 = blockIdx.x * 128 + (wid & 3) * 32;
    int n_base = (wid >> 2) * 64;
    const float2* x2 = (const float2*)X;

    float acc[2][8][4];
#pragma unroll
    for (int mt = 0; mt < 2; mt++)
#pragma unroll
        for (int nt = 0; nt < 8; nt++)
#pragma unroll
            for (int j = 0; j < 4; j++) acc[mt][nt][j] = 0.f;

#pragma unroll
    for (int ks = 0; ks < 8; ks++) {
        int kw = ks * 8 + t4;
        uint32_t ahi[2][4], alo[2][4];
#pragma unroll
        for (int mt = 0; mt < 2; mt++) {
            int r = m0 + mt * 16 + g;
            float2 z2 = make_float2(0.f, 0.f);
            float2 v0 = (r < M)     ? __ldg(x2 + (size_t)r * DW + kw)           : z2;
            float2 v1 = (r + 8 < M) ? __ldg(x2 + (size_t)(r + 8) * DW + kw)     : z2;
            float2 v2 = (r < M)     ? __ldg(x2 + (size_t)r * DW + kw + 4)       : z2;
            float2 v3 = (r + 8 < M) ? __ldg(x2 + (size_t)(r + 8) * DW + kw + 4) : z2;
            split_pack(v0.x, v0.y, ahi[mt][0], alo[mt][0]);
            split_pack(v1.x, v1.y, ahi[mt][1], alo[mt][1]);
            split_pack(v2.x, v2.y, ahi[mt][2], alo[mt][2]);
            split_pack(v3.x, v3.y, ahi[mt][3], alo[mt][3]);
        }
#pragma unroll
        for (int nt = 0; nt < 8; nt++) {
            size_t nb = (size_t)(n_base + nt * 8 + g) * DW + kw;
            uint32_t bh0 = __ldg(Bhi + nb);
            uint32_t bh1 = __ldg(Bhi + nb + 4);
            uint32_t bl0 = __ldg(Blo + nb);
            uint32_t bl1 = __ldg(Blo + nb + 4);
#pragma unroll
            for (int mt = 0; mt < 2; mt++) {
                mma_bf16(acc[mt][nt], ahi[mt], bh0, bh1);
                mma_bf16(acc[mt][nt], ahi[mt], bl0, bl1);
                mma_bf16(acc[mt][nt], alo[mt], bh0, bh1);
            }
        }
    }

#pragma unroll
    for (int mt = 0; mt < 2; mt++) {
        int r0 = m0 + mt * 16 + g;
#pragma unroll
        for (int nt = 0; nt < 8; nt++) {
            int n = n_base + nt * 8 + t4 * 2;
            if (r0 < M)
                *(float2*)(C + (size_t)r0 * D + n) =
                    make_float2(acc[mt][nt][0], acc[mt][nt][1]);
            if (r0 + 8 < M)
                *(float2*)(C + (size_t)(r0 + 8) * D + n) =
                    make_float2(acc[mt][nt][2], acc[mt][nt][3]);
        }
    }
}

// Layer-2 GEMM: A read from pre-split hi/lo tables; row_off selects the half.
__global__ void __launch_bounds__(256, 2)
k_gemm_mma(const uint32_t* __restrict__ Bhi, const uint32_t* __restrict__ Blo,
           float* __restrict__ C, int M, int row_off) {
    int tid = threadIdx.x, wid = tid >> 5, lane = tid & 31;
    int g = lane >> 2, t4 = lane & 3;
    int m0 = row_off + blockIdx.x * 128 + (wid & 3) * 32;
    int n_base = (wid >> 2) * 64;

    float acc[2][8][4];
#pragma unroll
    for (int mt = 0; mt < 2; mt++)
#pragma unroll
        for (int nt = 0; nt < 8; nt++)
#pragma unroll
            for (int j = 0; j < 4; j++) acc[mt][nt][j] = 0.f;

#pragma unroll
    for (int ks = 0; ks < 8; ks++) {
        int kw = ks * 8 + t4;
        uint32_t ahi[2][4], alo[2][4];
#pragma unroll
        for (int mt = 0; mt < 2; mt++) {
            size_t base = (size_t)(m0 + mt * 16 + g) * DW + kw;
            ahi[mt][0] = __ldg(g_ahi + base);
            ahi[mt][1] = __ldg(g_ahi + base + 8 * DW);
            ahi[mt][2] = __ldg(g_ahi + base + 4);
            ahi[mt][3] = __ldg(g_ahi + base + 8 * DW + 4);
            alo[mt][0] = __ldg(g_alo + base);
            alo[mt][1] = __ldg(g_alo + base + 8 * DW);
            alo[mt][2] = __ldg(g_alo + base + 4);
            alo[mt][3] = __ldg(g_alo + base + 8 * DW + 4);
        }
#pragma unroll
        for (int nt = 0; nt < 8; nt++) {
            size_t nb = (size_t)(n_base + nt * 8 + g) * DW + kw;
            uint32_t bh0 = __ldg(Bhi + nb);
            uint32_t bh1 = __ldg(Bhi + nb + 4);
            uint32_t bl0 = __ldg(Blo + nb);
            uint32_t bl1 = __ldg(Blo + nb + 4);
#pragma unroll
            for (int mt = 0; mt < 2; mt++) {
                mma_bf16(acc[mt][nt], ahi[mt], bh0, bh1);
                mma_bf16(acc[mt][nt], ahi[mt], bl0, bl1);
                mma_bf16(acc[mt][nt], alo[mt], bh0, bh1);
            }
        }
    }

#pragma unroll
    for (int mt = 0; mt < 2; mt++) {
        int r0 = m0 + mt * 16 + g;
#pragma unroll
        for (int nt = 0; nt < 8; nt++) {
            int n = n_base + nt * 8 + t4 * 2;
            if (r0 < M)
                *(float2*)(C + (size_t)r0 * D + n) =
                    make_float2(acc[mt][nt][0], acc[mt][nt][1]);
            if (r0 + 8 < M)
                *(float2*)(C + (size_t)(r0 + 8) * D + n) =
                    make_float2(acc[mt][nt][2], acc[mt][nt][3]);
        }
    }
}

// ---------------- CSR aggregation: z[n] = sum_{e->n} h[src]*w + self -------
// One warp per node. Fixed 32-iteration inner loop (invalid lanes carry
// src=0, w=0.0f) so ptxas fully unrolls and batches the gathers -> high MLP.
// conv_mode=1: write relu(z + bias) as split-bf16 into the A tables.
__global__ void __launch_bounds__(256)
k_agg_csr(const float* __restrict__ h, float* __restrict__ z,
          const float* __restrict__ bias, int conv_mode,
          int node_off, int node_end) {
    int gw   = (blockIdx.x * blockDim.x + threadIdx.x) >> 5;
    int lane = threadIdx.x & 31;
    int n = node_off + gw;
    if (n >= node_end) return;

    float di = g_dinv[n];
    float ws = di * di;
    float4 hv = ((const float4*)h)[(size_t)n * D4 + lane];
    float4 acc = make_float4(hv.x * ws, hv.y * ws, hv.z * ws, hv.w * ws);

    int s0 = g_rowptr[n];
    int s1 = g_rowptr[n + 1];
    for (int base = s0; base < s1; base += 32) {
        int i = base + lane;
        int   es = 0;
        float ew = 0.f;
        if (i < s1) {
            int2 ed = g_csr[i];
            es = ed.x;
            ew = __int_as_float(ed.y);
        }
#pragma unroll 8
        for (int j = 0; j < 32; j++) {
            int   sj = __shfl_sync(0xFFFFFFFFu, es, j);
            float wj = __shfl_sync(0xFFFFFFFFu, ew, j);
            float4 v = ((const float4*)h)[(size_t)sj * D4 + lane];
            acc.x = fmaf(v.x, wj, acc.x);
            acc.y = fmaf(v.y, wj, acc.y);
            acc.z = fmaf(v.z, wj, acc.z);
            acc.w = fmaf(v.w, wj, acc.w);
        }
    }

    if (conv_mode) {
        float4 b = ((const float4*)bias)[lane];
        float v0 = fmaxf(acc.x + b.x, 0.f);
        float v1 = fmaxf(acc.y + b.y, 0.f);
        float v2 = fmaxf(acc.z + b.z, 0.f);
        float v3 = fmaxf(acc.w + b.w, 0.f);
        uint32_t hi0, lo0, hi1, lo1;
        split_pack(v0, v1, hi0, lo0);
        split_pack(v2, v3, hi1, lo1);
        size_t base = (size_t)n * DW + lane * 2;
        g_ahi[base]     = hi0;
        g_ahi[base + 1] = hi1;
        g_alo[base]     = lo0;
        g_alo[base + 1] = lo1;
    } else {
        ((float4*)z)[(size_t)n * D4 + lane] = acc;
    }
}

// ---------------- decode: logits[e] = dot(z[s]+b2, z[d]+b2) ----------------
__global__ void __launch_bounds__(256) k_decode(const void* __restrict__ lab,
                                                const float* __restrict__ b2,
                                                float* __restrict__ out) {
    int gwarp  = (blockIdx.x * blockDim.x + threadIdx.x) >> 5;
    int lane   = threadIdx.x & 31;
    int nwarps = (gridDim.x * blockDim.x) >> 5;
    float4 b = ((const float4*)b2)[lane];
    for (int e = gwarp; e < N_LAB; e += nwarps) {
        int s = load_idx(lab, e);
        int d = load_idx(lab, (size_t)N_LAB + e);
        float4 a = ((const float4*)g_z)[(size_t)s * D4 + lane];
        float4 c = ((const float4*)g_z)[(size_t)d * D4 + lane];
        float sum = (a.x + b.x) * (c.x + b.x)
                  + (a.y + b.y) * (c.y + b.y)
                  + (a.z + b.z) * (c.z + b.z)
                  + (a.w + b.w) * (c.w + b.w);
#pragma unroll
        for (int off = 16; off; off >>= 1)
            sum += __shfl_xor_sync(0xFFFFFFFFu, sum, off);
        if (lane == 0) out[e] = sum;
    }
}

// ---------------- launch ---------------------------------------------------
extern "C" void kernel_launch(void* const* d_in, const int* in_sizes, int n_in,
                              void* d_out, int out_size) {
    const float* x   = (const float*)d_in[0];
    const void*  ei  = d_in[1];               // int32 or int64, autodetected
    const void*  lab = d_in[2];
    const float* W1  = (const float*)d_in[3];
    const float* b1  = (const float*)d_in[4];
    const float* W2  = (const float*)d_in[5];
    const float* b2  = (const float*)d_in[6];
    float*       out = (float*)d_out;

    (void)in_sizes; (void)n_in; (void)out_size;

    static cudaStream_t side = nullptr;
    static cudaEvent_t  e_fork = nullptr, e_join = nullptr,
                        e_aggA = nullptr, e_g2A = nullptr;
    if (!side) {
        cudaStreamCreate(&side);
        cudaEventCreateWithFlags(&e_fork, cudaEventDisableTiming);
        cudaEventCreateWithFlags(&e_join, cudaEventDisableTiming);
        cudaEventCreateWithFlags(&e_aggA, cudaEventDisableTiming);
        cudaEventCreateWithFlags(&e_g2A, cudaEventDisableTiming);
    }

    float *hptr = nullptr, *zptr = nullptr;
    uint32_t *w1hi, *w1lo, *w2hi, *w2lo;
    cudaGetSymbolAddress((void**)&hptr, g_h);
    cudaGetSymbolAddress((void**)&zptr, g_z);
    cudaGetSymbolAddress((void**)&w1hi, g_w1hi);
    cudaGetSymbolAddress((void**)&w1lo, g_w1lo);
    cudaGetSymbolAddress((void**)&w2hi, g_w2hi);
    cudaGetSymbolAddress((void**)&w2lo, g_w2lo);

    const int T = 256;
    const int NODE_BLOCKS = (N_NODES + T - 1) / T;   // 391
    const int EDGE_BLOCKS = (N_EDGES + T - 1) / T;
    const int DEC_BLOCKS  = 1184;
    const int AGG_A = NHALF / 8;                     // 6256
    const int AGG_B = (N_NODES - NHALF + 7) / 8;     // 6244
    const int G2_A  = NHALF / 128;                   // 391
    const int G2_B  = GEMM_CTAS - G2_A;              // 391

    // ---- fork: prep chain on side stream ----------------------------------
    cudaEventRecord(e_fork, 0);
    cudaStreamWaitEvent(side, e_fork, 0);
    k_detect_init<<<NODE_BLOCKS, T, 0, side>>>((const int*)ei);
    k_cnt_acc    <<<EDGE_BLOCKS, T, 0, side>>>(ei);
    k_dinv       <<<NODE_BLOCKS, T, 0, side>>>();
    k_scan_block <<<NB, 256, 0, side>>>();
    k_scan_top   <<<1, 512, 0, side>>>();
    k_scan_add   <<<NODE_BLOCKS, T, 0, side>>>();
    k_fill       <<<EDGE_BLOCKS, T, 0, side>>>(ei);
    cudaEventRecord(e_join, side);

    // ---- main stream: W conversion + layer-1 GEMM (fp32-fused) ------------
    k_wconv <<<64, T>>>(W1, W2);
    k_gemm_x<<<GEMM_CTAS, T>>>(x, w1hi, w1lo, hptr, N_NODES);

    // ---- join, then agg1 first half; gemm2 first half overlaps agg1_B -----
    cudaStreamWaitEvent(0, e_join, 0);
    k_agg_csr<<<AGG_A, T>>>(hptr, zptr, b1, 1, 0, NHALF);
    cudaEventRecord(e_aggA, 0);

    cudaStreamWaitEvent(side, e_aggA, 0);
    k_gemm_mma<<<G2_A, T, 0, side>>>(w2hi, w2lo, hptr, N_NODES, 0);
    cudaEventRecord(e_g2A, side);

    k_agg_csr <<<AGG_B, T>>>(hptr, zptr, b1, 1, NHALF, N_NODES);
    k_gemm_mma<<<G2_B, T>>>(w2hi, w2lo, hptr, N_NODES, NHALF);
    cudaStreamWaitEvent(0, e_g2A, 0);

    // ---- agg2 + decode -----------------------------------------------------
    k_agg_csr<<<(N_NODES + 7) / 8, T>>>(hptr, zptr, nullptr, 0, 0, N_NODES);
    k_decode <<<DEC_BLOCKS, T>>>(lab, b2, out);
}

// round 15
// speedup vs baseline: 1.0982x; 1.0982x over previous
#include <cuda_runtime.h>
#include <cuda_bf16.h>
#include <cstdint>

#define N_NODES 100000
#define N_EDGES 1600000
#define N_LAB   200000
#define D       128
#define D4      32    // D/4 floats
#define DW      64    // D/2 = 32-bit words per row of bf16
#define NB      391   // ceil(N_NODES / 256)
#define GEMM_CTAS 782
#define NHALF   50048 // 391 * 128 (CTA-aligned node split)

// ---------------- static device scratch (no allocations allowed) ----------
__device__ float    g_h[(size_t)N_NODES * D];  // GEMM output (pre-aggregation)
__device__ float    g_z[(size_t)N_NODES * D];  // final aggregated features
__device__ float    g_dinv[N_NODES];
__device__ int      g_cnt[N_NODES];
__device__ int      g_rowptr[N_NODES + 1];
__device__ int      g_cursor[N_NODES];
__device__ int      g_bsum[NB];
__device__ int      g_boff[NB];
__device__ int2     g_csr[N_EDGES];            // {src, bitcast(norm weight)}
__device__ int      g_is64;
// split-bf16 A tables for layer 2 (written by agg1; padding rows stay 0)
__device__ uint32_t g_ahi[(size_t)GEMM_CTAS * 128 * DW];
__device__ uint32_t g_alo[(size_t)GEMM_CTAS * 128 * DW];
__device__ uint32_t g_w1hi[D * DW], g_w1lo[D * DW];  // (n, kword)
__device__ uint32_t g_w2hi[D * DW], g_w2lo[D * DW];

// ---------------- helpers --------------------------------------------------
__device__ __forceinline__ void split_pack(float v0, float v1,
                                           uint32_t& hi, uint32_t& lo) {
    __nv_bfloat16 h0 = __float2bfloat16(v0);
    __nv_bfloat16 h1 = __float2bfloat16(v1);
    __nv_bfloat16 l0 = __float2bfloat16(v0 - __bfloat162float(h0));
    __nv_bfloat16 l1 = __float2bfloat16(v1 - __bfloat162float(h1));
    hi = (uint32_t)__bfloat16_as_ushort(h0) |
         ((uint32_t)__bfloat16_as_ushort(h1) << 16);
    lo = (uint32_t)__bfloat16_as_ushort(l0) |
         ((uint32_t)__bfloat16_as_ushort(l1) << 16);
}

// ---------------- dtype autodetect + counter init (fused) ------------------
__global__ void k_detect_init(const int* __restrict__ ei_raw) {
    int i = blockIdx.x * blockDim.x + threadIdx.x;
    if (i < N_NODES) g_cnt[i] = 0;
    if (i == 0) {
        int all_zero = 1;
        for (int j = 0; j < 32; j++)
            if (ei_raw[2 * j + 1] != 0) { all_zero = 0; break; }
        g_is64 = all_zero;
    }
}

__device__ __forceinline__ int load_idx(const void* p, size_t i) {
    return g_is64 ? (int)((const long long*)p)[i] : ((const int*)p)[i];
}

// ---------------- degree / norm prep --------------------------------------
__global__ void k_cnt_acc(const void* __restrict__ ei) {
    int e = blockIdx.x * blockDim.x + threadIdx.x;
    if (e < N_EDGES) atomicAdd(&g_cnt[load_idx(ei, (size_t)N_EDGES + e)], 1);
}

__global__ void k_dinv() {
    int i = blockIdx.x * blockDim.x + threadIdx.x;
    if (i < N_NODES) g_dinv[i] = rsqrtf((float)(g_cnt[i] + 1));  // +1 self loop
}

// ---------------- CSR build: 3-kernel prefix sum + binned fill -------------
__global__ void k_scan_block() {
    __shared__ int sm[256];
    int b = blockIdx.x, t = threadIdx.x;
    int i = b * 256 + t;
    int v = (i < N_NODES) ? g_cnt[i] : 0;
    sm[t] = v;
    __syncthreads();
    for (int off = 1; off < 256; off <<= 1) {
        int add = (t >= off) ? sm[t - off] : 0;
        __syncthreads();
        sm[t] += add;
        __syncthreads();
    }
    if (i < N_NODES) g_rowptr[i] = sm[t] - v;
    if (t == 255)    g_bsum[b] = sm[255];
}

__global__ void k_scan_top() {
    __shared__ int sm[512];
    int t = threadIdx.x;
    int v = (t < NB) ? g_bsum[t] : 0;
    sm[t] = v;
    __syncthreads();
    for (int off = 1; off < 512; off <<= 1) {
        int add = (t >= off) ? sm[t - off] : 0;
        __syncthreads();
        sm[t] += add;
        __syncthreads();
    }
    if (t < NB) g_boff[t] = sm[t] - v;
    if (t == 0) g_rowptr[N_NODES] = sm[511];
}

__global__ void k_scan_add() {
    int i = blockIdx.x * blockDim.x + threadIdx.x;
    if (i < N_NODES) {
        int r = g_rowptr[i] + g_boff[i >> 8];
        g_rowptr[i] = r;
        g_cursor[i] = r;
    }
}

__global__ void k_fill(const void* __restrict__ ei) {
    int e = blockIdx.x * blockDim.x + threadIdx.x;
    if (e < N_EDGES) {
        int s = load_idx(ei, e);
        int d = load_idx(ei, (size_t)N_EDGES + e);
        float w = g_dinv[s] * g_dinv[d];
        int pos = atomicAdd(&g_cursor[d], 1);
        g_csr[pos] = make_int2(s, __float_as_int(w));
    }
}

// ---------------- W conversion (once per call, tiny) -----------------------
__global__ void k_wconv(const float* __restrict__ W1,
                        const float* __restrict__ W2) {
    int idx = blockIdx.x * 256 + threadIdx.x;      // 0..16383
    int mat = idx >> 13;
    int j = idx & 8191;
    int n = j >> 6, kw = j & 63;
    const float* Wm = mat ? W2 : W1;
    float v0 = Wm[(size_t)(2 * kw) * D + n];
    float v1 = Wm[(size_t)(2 * kw + 1) * D + n];
    uint32_t hi, lo;
    split_pack(v0, v1, hi, lo);
    if (mat) { g_w2hi[j] = hi; g_w2lo[j] = lo; }
    else     { g_w1hi[j] = hi; g_w1lo[j] = lo; }
}

// ================= HMMA GEMM (mma.sync, split-bf16 x3) =====================
__device__ __forceinline__ void mma_bf16(float* d, const uint32_t* a,
                                         uint32_t b0, uint32_t b1) {
    asm volatile(
        "mma.sync.aligned.m16n8k16.row.col.f32.bf16.bf16.f32 "
        "{%0,%1,%2,%3}, {%4,%5,%6,%7}, {%8,%9}, {%0,%1,%2,%3};"
        : "+f"(d[0]), "+f"(d[1]), "+f"(d[2]), "+f"(d[3])
        : "r"(a[0]), "r"(a[1]), "r"(a[2]), "r"(a[3]), "r"(b0), "r"(b1));
}

// Layer-1 GEMM: A = fp32 x, converted to split-bf16 in-register.
__global__ void __launch_bounds__(256, 2)
k_gemm_x(const float* __restrict__ X,
         const uint32_t* __restrict__ Bhi, const uint32_t* __restrict__ Blo,
         float* __restrict__ C, int M) {
    int tid = threadIdx.x, wid = tid >> 5, lane = tid & 31;
    int g = lane >> 2, t4 = lane & 3;
    int m0 = blockIdx.x * 128 + (wid & 3) * 32;
    int n_base = (wid >> 2) * 64;
    const float2* x2 = (const float2*)X;

    float acc[2][8][4];
#pragma unroll
    for (int mt = 0; mt < 2; mt++)
#pragma unroll
        for (int nt = 0; nt < 8; nt++)
#pragma unroll
            for (int j = 0; j < 4; j++) acc[mt][nt][j] = 0.f;

#pragma unroll
    for (int ks = 0; ks < 8; ks++) {
        int kw = ks * 8 + t4;
        uint32_t ahi[2][4], alo[2][4];
#pragma unroll
        for (int mt = 0; mt < 2; mt++) {
            int r = m0 + mt * 16 + g;
            float2 z2 = make_float2(0.f, 0.f);
            float2 v0 = (r < M)     ? __ldg(x2 + (size_t)r * DW + kw)           : z2;
            float2 v1 = (r + 8 < M) ? __ldg(x2 + (size_t)(r + 8) * DW + kw)     : z2;
            float2 v2 = (r < M)     ? __ldg(x2 + (size_t)r * DW + kw + 4)       : z2;
            float2 v3 = (r + 8 < M) ? __ldg(x2 + (size_t)(r + 8) * DW + kw + 4) : z2;
            split_pack(v0.x, v0.y, ahi[mt][0], alo[mt][0]);
            split_pack(v1.x, v1.y, ahi[mt][1], alo[mt][1]);
            split_pack(v2.x, v2.y, ahi[mt][2], alo[mt][2]);
            split_pack(v3.x, v3.y, ahi[mt][3], alo[mt][3]);
        }
#pragma unroll
        for (int nt = 0; nt < 8; nt++) {
            size_t nb = (size_t)(n_base + nt * 8 + g) * DW + kw;
            uint32_t bh0 = __ldg(Bhi + nb);
            uint32_t bh1 = __ldg(Bhi + nb + 4);
            uint32_t bl0 = __ldg(Blo + nb);
            uint32_t bl1 = __ldg(Blo + nb + 4);
#pragma unroll
            for (int mt = 0; mt < 2; mt++) {
                mma_bf16(acc[mt][nt], ahi[mt], bh0, bh1);
                mma_bf16(acc[mt][nt], ahi[mt], bl0, bl1);
                mma_bf16(acc[mt][nt], alo[mt], bh0, bh1);
            }
        }
    }

#pragma unroll
    for (int mt = 0; mt < 2; mt++) {
        int r0 = m0 + mt * 16 + g;
#pragma unroll
        for (int nt = 0; nt < 8; nt++) {
            int n = n_base + nt * 8 + t4 * 2;
            if (r0 < M)
                *(float2*)(C + (size_t)r0 * D + n) =
                    make_float2(acc[mt][nt][0], acc[mt][nt][1]);
            if (r0 + 8 < M)
                *(float2*)(C + (size_t)(r0 + 8) * D + n) =
                    make_float2(acc[mt][nt][2], acc[mt][nt][3]);
        }
    }
}

// Layer-2 GEMM: A read from pre-split hi/lo tables; row_off selects the half.
__global__ void __launch_bounds__(256, 2)
k_gemm_mma(const uint32_t* __restrict__ Bhi, const uint32_t* __restrict__ Blo,
           float* __restrict__ C, int M, int row_off) {
    int tid = threadIdx.x, wid = tid >> 5, lane = tid & 31;
    int g = lane >> 2, t4 = lane & 3;
    int m0 = row_off + blockIdx.x * 128 + (wid & 3) * 32;
    int n_base = (wid >> 2) * 64;

    float acc[2][8][4];
#pragma unroll
    for (int mt = 0; mt < 2; mt++)
#pragma unroll
        for (int nt = 0; nt < 8; nt++)
#pragma unroll
            for (int j = 0; j < 4; j++) acc[mt][nt][j] = 0.f;

#pragma unroll
    for (int ks = 0; ks < 8; ks++) {
        int kw = ks * 8 + t4;
        uint32_t ahi[2][4], alo[2][4];
#pragma unroll
        for (int mt = 0; mt < 2; mt++) {
            size_t base = (size_t)(m0 + mt * 16 + g) * DW + kw;
            ahi[mt][0] = __ldg(g_ahi + base);
            ahi[mt][1] = __ldg(g_ahi + base + 8 * DW);
            ahi[mt][2] = __ldg(g_ahi + base + 4);
            ahi[mt][3] = __ldg(g_ahi + base + 8 * DW + 4);
            alo[mt][0] = __ldg(g_alo + base);
            alo[mt][1] = __ldg(g_alo + base + 8 * DW);
            alo[mt][2] = __ldg(g_alo + base + 4);
            alo[mt][3] = __ldg(g_alo + base + 8 * DW + 4);
        }
#pragma unroll
        for (int nt = 0; nt < 8; nt++) {
            size_t nb = (size_t)(n_base + nt * 8 + g) * DW + kw;
            uint32_t bh0 = __ldg(Bhi + nb);
            uint32_t bh1 = __ldg(Bhi + nb + 4);
            uint32_t bl0 = __ldg(Blo + nb);
            uint32_t bl1 = __ldg(Blo + nb + 4);
#pragma unroll
            for (int mt = 0; mt < 2; mt++) {
                mma_bf16(acc[mt][nt], ahi[mt], bh0, bh1);
                mma_bf16(acc[mt][nt], ahi[mt], bl0, bl1);
                mma_bf16(acc[mt][nt], alo[mt], bh0, bh1);
            }
        }
    }

#pragma unroll
    for (int mt = 0; mt < 2; mt++) {
        int r0 = m0 + mt * 16 + g;
#pragma unroll
        for (int nt = 0; nt < 8; nt++) {
            int n = n_base + nt * 8 + t4 * 2;
            if (r0 < M)
                *(float2*)(C + (size_t)r0 * D + n) =
                    make_float2(acc[mt][nt][0], acc[mt][nt][1]);
            if (r0 + 8 < M)
                *(float2*)(C + (size_t)(r0 + 8) * D + n) =
                    make_float2(acc[mt][nt][2], acc[mt][nt][3]);
        }
    }
}

// ---------------- CSR aggregation: z[n] = sum_{e->n} h[src]*w + self -------
// One warp per node. Edges processed in chunks of 8 with a fixed, fully
// unrolled body (invalid lanes carry src=0, w=0.0f so tail pad iterations
// are no-ops): ~8 independent gathers in flight without doubling work.
// conv_mode=1: write relu(z + bias) as split-bf16 into the A tables.
__global__ void __launch_bounds__(256)
k_agg_csr(const float* __restrict__ h, float* __restrict__ z,
          const float* __restrict__ bias, int conv_mode,
          int node_off, int node_end) {
    int gw   = (blockIdx.x * blockDim.x + threadIdx.x) >> 5;
    int lane = threadIdx.x & 31;
    int n = node_off + gw;
    if (n >= node_end) return;

    float di = g_dinv[n];
    float ws = di * di;
    float4 hv = ((const float4*)h)[(size_t)n * D4 + lane];
    float4 acc = make_float4(hv.x * ws, hv.y * ws, hv.z * ws, hv.w * ws);

    int s0 = g_rowptr[n];
    int s1 = g_rowptr[n + 1];
    for (int base = s0; base < s1; base += 32) {
        int i = base + lane;
        int   es = 0;
        float ew = 0.f;
        if (i < s1) {
            int2 ed = g_csr[i];
            es = ed.x;
            ew = __int_as_float(ed.y);
        }
        int cnt = min(32, s1 - base);
        for (int jb = 0; jb < cnt; jb += 8) {
#pragma unroll
            for (int jj = 0; jj < 8; jj++) {
                int j = jb + jj;
                int   sj = __shfl_sync(0xFFFFFFFFu, es, j);
                float wj = __shfl_sync(0xFFFFFFFFu, ew, j);
                float4 v = ((const float4*)h)[(size_t)sj * D4 + lane];
                acc.x = fmaf(v.x, wj, acc.x);
                acc.y = fmaf(v.y, wj, acc.y);
                acc.z = fmaf(v.z, wj, acc.z);
                acc.w = fmaf(v.w, wj, acc.w);
            }
        }
    }

    if (conv_mode) {
        float4 b = ((const float4*)bias)[lane];
        float v0 = fmaxf(acc.x + b.x, 0.f);
        float v1 = fmaxf(acc.y + b.y, 0.f);
        float v2 = fmaxf(acc.z + b.z, 0.f);
        float v3 = fmaxf(acc.w + b.w, 0.f);
        uint32_t hi0, lo0, hi1, lo1;
        split_pack(v0, v1, hi0, lo0);
        split_pack(v2, v3, hi1, lo1);
        size_t base = (size_t)n * DW + lane * 2;
        g_ahi[base]     = hi0;
        g_ahi[base + 1] = hi1;
        g_alo[base]     = lo0;
        g_alo[base + 1] = lo1;
    } else {
        ((float4*)z)[(size_t)n * D4 + lane] = acc;
    }
}

// ---------------- decode: logits[e] = dot(z[s]+b2, z[d]+b2) ----------------
__global__ void __launch_bounds__(256) k_decode(const void* __restrict__ lab,
                                                const float* __restrict__ b2,
                                                float* __restrict__ out) {
    int gwarp  = (blockIdx.x * blockDim.x + threadIdx.x) >> 5;
    int lane   = threadIdx.x & 31;
    int nwarps = (gridDim.x * blockDim.x) >> 5;
    float4 b = ((const float4*)b2)[lane];
    for (int e = gwarp; e < N_LAB; e += nwarps) {
        int s = load_idx(lab, e);
        int d = load_idx(lab, (size_t)N_LAB + e);
        float4 a = ((const float4*)g_z)[(size_t)s * D4 + lane];
        float4 c = ((const float4*)g_z)[(size_t)d * D4 + lane];
        float sum = (a.x + b.x) * (c.x + b.x)
                  + (a.y + b.y) * (c.y + b.y)
                  + (a.z + b.z) * (c.z + b.z)
                  + (a.w + b.w) * (c.w + b.w);
#pragma unroll
        for (int off = 16; off; off >>= 1)
            sum += __shfl_xor_sync(0xFFFFFFFFu, sum, off);
        if (lane == 0) out[e] = sum;
    }
}

// ---------------- launch ---------------------------------------------------
extern "C" void kernel_launch(void* const* d_in, const int* in_sizes, int n_in,
                              void* d_out, int out_size) {
    const float* x   = (const float*)d_in[0];
    const void*  ei  = d_in[1];               // int32 or int64, autodetected
    const void*  lab = d_in[2];
    const float* W1  = (const float*)d_in[3];
    const float* b1  = (const float*)d_in[4];
    const float* W2  = (const float*)d_in[5];
    const float* b2  = (const float*)d_in[6];
    float*       out = (float*)d_out;

    (void)in_sizes; (void)n_in; (void)out_size;

    static cudaStream_t side = nullptr;
    static cudaEvent_t  e_fork = nullptr, e_join = nullptr,
                        e_aggA = nullptr, e_g2A = nullptr;
    if (!side) {
        cudaStreamCreate(&side);
        cudaEventCreateWithFlags(&e_fork, cudaEventDisableTiming);
        cudaEventCreateWithFlags(&e_join, cudaEventDisableTiming);
        cudaEventCreateWithFlags(&e_aggA, cudaEventDisableTiming);
        cudaEventCreateWithFlags(&e_g2A, cudaEventDisableTiming);
    }

    float *hptr = nullptr, *zptr = nullptr;
    uint32_t *w1hi, *w1lo, *w2hi, *w2lo;
    cudaGetSymbolAddress((void**)&hptr, g_h);
    cudaGetSymbolAddress((void**)&zptr, g_z);
    cudaGetSymbolAddress((void**)&w1hi, g_w1hi);
    cudaGetSymbolAddress((void**)&w1lo, g_w1lo);
    cudaGetSymbolAddress((void**)&w2hi, g_w2hi);
    cudaGetSymbolAddress((void**)&w2lo, g_w2lo);

    const int T = 256;
    const int NODE_BLOCKS = (N_NODES + T - 1) / T;   // 391
    const int EDGE_BLOCKS = (N_EDGES + T - 1) / T;
    const int DEC_BLOCKS  = 1184;
    const int AGG_A = NHALF / 8;                     // 6256
    const int AGG_B = (N_NODES - NHALF + 7) / 8;     // 6244
    const int G2_A  = NHALF / 128;                   // 391
    const int G2_B  = GEMM_CTAS - G2_A;              // 391

    // ---- fork: prep chain on side stream ----------------------------------
    cudaEventRecord(e_fork, 0);
    cudaStreamWaitEvent(side, e_fork, 0);
    k_detect_init<<<NODE_BLOCKS, T, 0, side>>>((const int*)ei);
    k_cnt_acc    <<<EDGE_BLOCKS, T, 0, side>>>(ei);
    k_dinv       <<<NODE_BLOCKS, T, 0, side>>>();
    k_scan_block <<<NB, 256, 0, side>>>();
    k_scan_top   <<<1, 512, 0, side>>>();
    k_scan_add   <<<NODE_BLOCKS, T, 0, side>>>();
    k_fill       <<<EDGE_BLOCKS, T, 0, side>>>(ei);
    cudaEventRecord(e_join, side);

    // ---- main stream: W conversion + layer-1 GEMM (fp32-fused) ------------
    k_wconv <<<64, T>>>(W1, W2);
    k_gemm_x<<<GEMM_CTAS, T>>>(x, w1hi, w1lo, hptr, N_NODES);

    // ---- join, then agg1 first half; gemm2 first half overlaps agg1_B -----
    cudaStreamWaitEvent(0, e_join, 0);
    k_agg_csr<<<AGG_A, T>>>(hptr, zptr, b1, 1, 0, NHALF);
    cudaEventRecord(e_aggA, 0);

    cudaStreamWaitEvent(side, e_aggA, 0);
    k_gemm_mma<<<G2_A, T, 0, side>>>(w2hi, w2lo, hptr, N_NODES, 0);
    cudaEventRecord(e_g2A, side);

    k_agg_csr <<<AGG_B, T>>>(hptr, zptr, b1, 1, NHALF, N_NODES);
    k_gemm_mma<<<G2_B, T>>>(w2hi, w2lo, hptr, N_NODES, NHALF);
    cudaStreamWaitEvent(0, e_g2A, 0);

    // ---- agg2 + decode -----------------------------------------------------
    k_agg_csr<<<(N_NODES + 7) / 8, T>>>(hptr, zptr, nullptr, 0, 0, N_NODES);
    k_decode <<<DEC_BLOCKS, T>>>(lab, b2, out);
}